// round 16
// baseline (speedup 1.0000x reference)
#include <cuda_runtime.h>
#include <math.h>

#define BDIM 2048
#define ODIM 256
#define IDIM 256

typedef unsigned long long u64;
typedef unsigned int u32;

// Scratch. g_u[j][b] = -K*cos(phi0+x[b,j]); g_v[j][b] = K*sin(phi0+x[b,j])
// g_p[j][i] = cos(off[i,j]); g_q[j][i] = sin(off[i,j])
__device__ float g_u[IDIM * BDIM];
__device__ float g_v[IDIM * BDIM];
__device__ float g_p[IDIM * ODIM];
__device__ float g_q[IDIM * ODIM];

// ---------- packed f32x2 helpers ----------
__device__ __forceinline__ u64 fma2(u64 a, u64 b, u64 c) {
    u64 d;
    asm("fma.rn.f32x2 %0, %1, %2, %3;" : "=l"(d) : "l"(a), "l"(b), "l"(c));
    return d;
}
__device__ __forceinline__ u64 add2(u64 a, u64 b) {
    u64 d;
    asm("add.rn.f32x2 %0, %1, %2;" : "=l"(d) : "l"(a), "l"(b));
    return d;
}
__device__ __forceinline__ u64 mul2(u64 a, u64 b) {
    u64 d;
    asm("mul.rn.f32x2 %0, %1, %2;" : "=l"(d) : "l"(a), "l"(b));
    return d;
}
__device__ __forceinline__ float frcp(float x) {
    float r;
    asm("rcp.approx.ftz.f32 %0, %1;" : "=f"(r) : "f"(x));
    return r;
}
__device__ __forceinline__ u64 rcp2(u64 x) {
    float lo, hi;
    asm("mov.b64 {%0, %1}, %2;" : "=f"(lo), "=f"(hi) : "l"(x));
    lo = frcp(lo);
    hi = frcp(hi);
    u64 r;
    asm("mov.b64 %0, {%1, %2};" : "=l"(r) : "f"(lo), "f"(hi));
    return r;
}
__device__ __forceinline__ u64 pack2(float lo, float hi) {
    u64 r;
    asm("mov.b64 %0, {%1, %2};" : "=l"(r) : "f"(lo), "f"(hi));
    return r;
}
__device__ __forceinline__ void unpack2(u64 v, float& lo, float& hi) {
    asm("mov.b64 {%0, %1}, %2;" : "=f"(lo), "=f"(hi) : "l"(v));
}

// fire-and-forget vector reduction (REDG.64), sm_90+
__device__ __forceinline__ void redadd2(float* p, float a, float b) {
    asm volatile("red.global.add.v2.f32 [%0], {%1, %2};" ::"l"(p), "f"(a),
                 "f"(b)
                 : "memory");
}

// ---------- cp.async (LDGSTS) ----------
__device__ __forceinline__ void cpasync16(u32 saddr, const void* gptr) {
    asm volatile("cp.async.cg.shared.global [%0], [%1], 16;" ::"r"(saddr),
                 "l"(gptr));
}
#define CP_COMMIT() asm volatile("cp.async.commit_group;" ::: "memory")
#define CP_WAIT(N) asm volatile("cp.async.wait_group %0;" ::"n"(N) : "memory")

// ---------- fused prep: uv transpose (512) + pq transpose (64) + init (512)
__global__ void prep_all(const float* __restrict__ x,
                         const float* __restrict__ off,
                         float* __restrict__ out, float K, float phi0) {
    const int bx = blockIdx.x;
    if (bx < 512) {
        __shared__ float tc[32][33];
        __shared__ float ts[32][33];
        const int b0 = (bx >> 3) * 32;
        const int j0 = (bx & 7) * 32;
#pragma unroll
        for (int k = 0; k < 4; k++) {
            int lin = threadIdx.x + k * 256;
            int bl = lin >> 5, jl = lin & 31;
            float s, c;
            __sincosf(phi0 + x[(b0 + bl) * IDIM + j0 + jl], &s, &c);
            tc[jl][bl] = c;
            ts[jl][bl] = s;
        }
        __syncthreads();
#pragma unroll
        for (int k = 0; k < 4; k++) {
            int lin = threadIdx.x + k * 256;
            int jl = lin >> 5, bl = lin & 31;
            g_u[(j0 + jl) * BDIM + b0 + bl] = -K * tc[jl][bl];
            g_v[(j0 + jl) * BDIM + b0 + bl] = K * ts[jl][bl];
        }
    } else if (bx < 576) {
        __shared__ float tc[32][33];
        __shared__ float ts[32][33];
        const int r = bx - 512;
        const int i0 = (r >> 3) * 32;
        const int j0 = (r & 7) * 32;
#pragma unroll
        for (int k = 0; k < 4; k++) {
            int lin = threadIdx.x + k * 256;
            int il = lin >> 5, jl = lin & 31;
            float s, c;
            __sincosf(off[(i0 + il) * IDIM + j0 + jl], &s, &c);
            tc[jl][il] = c;
            ts[jl][il] = s;
        }
        __syncthreads();
#pragma unroll
        for (int k = 0; k < 4; k++) {
            int lin = threadIdx.x + k * 256;
            int jl = lin >> 5, il = lin & 31;
            g_p[(j0 + jl) * ODIM + i0 + il] = tc[jl][il];
            g_q[(j0 + jl) * ODIM + i0 + il] = ts[jl][il];
        }
    } else {
        // init out = IDIM (base of T-sum); 512 blocks x 256 thr x float4
        int idx = (bx - 576) * 256 + threadIdx.x;
        float4 v = {(float)IDIM, (float)IDIM, (float)IDIM, (float)IDIM};
        ((float4*)out)[idx] = v;
    }
}

// quad-j combine: acc += (s01*m23 + s23*m01) * rcp(m01*m23)
#define QCOMB(ACC, D0, D1, D2, D3)                                      \
    do {                                                                \
        u64 s01 = add2(D0, D1), m01 = mul2(D0, D1);                     \
        u64 s23 = add2(D2, D3), m23 = mul2(D2, D3);                     \
        u64 num = fma2(s23, m01, mul2(s01, m23));                       \
        u64 den = mul2(m01, m23);                                       \
        ACC = fma2(num, rcp2(den), ACC);                                \
    } while (0)

// ---------- main: BM=64 x BN=32 x 32j work units, 128 threads --------------
// grid = 2048: bits[0:2] = k-part (32 j), bits[3..] = spatial (8 i x 32 b).
// Per thread: 8 b (4 packed slots) x 2 i -> 8 packed accumulators.
__global__ __launch_bounds__(128, 4) void photonic_main(float* __restrict__ out,
                                                        float C2, float D) {
    __shared__ float su[2][16][64];
    __shared__ float sv[2][16][64];
    __shared__ float sp[2][16][32];
    __shared__ float sq[2][16][32];

    const int tid = threadIdx.x;
    const int bg = tid & 7;    // 8 b-groups x 8 b
    const int ig = tid >> 3;   // 16 i-groups x 2 i
    const int kpart = blockIdx.x & 7;
    const int spat = blockIdx.x >> 3;  // 0..255
    const int i0 = (spat & 7) * 32;
    const int b0 = (spat >> 3) * 64;
    const int jbase = kpart * 32;

    const u64 C22 = pack2(C2, C2);
    u64 acc[4][2];  // [b-slot][i]
#pragma unroll
    for (int s = 0; s < 4; s++) {
        acc[s][0] = 0ull;
        acc[s][1] = 0ull;
    }

    auto cp_chunk = [&](int kc, int bf) {
        const int j0 = jbase + kc * 16;
        // su/sv: 1024 floats each -> 2 x 16B per thread
#pragma unroll
        for (int k = 0; k < 2; k++) {
            int idx = tid + 128 * k;
            int r = idx >> 4, c = (idx & 15) * 4;
            cpasync16((u32)__cvta_generic_to_shared(&su[bf][r][c]),
                      g_u + (size_t)(j0 + r) * BDIM + b0 + c);
            cpasync16((u32)__cvta_generic_to_shared(&sv[bf][r][c]),
                      g_v + (size_t)(j0 + r) * BDIM + b0 + c);
        }
        // sp/sq: 512 floats each -> 1 x 16B per thread
        {
            int r = tid >> 3, c = (tid & 7) * 4;
            cpasync16((u32)__cvta_generic_to_shared(&sp[bf][r][c]),
                      g_p + (size_t)(j0 + r) * ODIM + i0 + c);
            cpasync16((u32)__cvta_generic_to_shared(&sq[bf][r][c]),
                      g_q + (size_t)(j0 + r) * ODIM + i0 + c);
        }
        CP_COMMIT();
    };

    cp_chunk(0, 0);

    const int NCH = 2;  // 32 j / 16
    for (int c = 0; c < NCH; c++) {
        const int bf = c & 1;
        if (c + 1 < NCH) {
            cp_chunk(c + 1, bf ^ 1);
            CP_WAIT(1);
        } else {
            CP_WAIT(0);
        }
        __syncthreads();

#pragma unroll
        for (int jj = 0; jj < 16; jj += 4) {
            // P/Q dup-packs for this thread's 2 i, all 4 k (reused by 4 slots)
            u64 P[4][2], Q[4][2];
#pragma unroll
            for (int k = 0; k < 4; k++) {
                float2 p2 = *(const float2*)&sp[bf][jj + k][ig * 2];
                float2 q2 = *(const float2*)&sq[bf][jj + k][ig * 2];
                P[k][0] = pack2(p2.x, p2.x);
                P[k][1] = pack2(p2.y, p2.y);
                Q[k][0] = pack2(q2.x, q2.x);
                Q[k][1] = pack2(q2.y, q2.y);
            }
            // process 4 b-slots in 2 halves to bound register pressure
#pragma unroll
            for (int h = 0; h < 2; h++) {
                u64 d[2][2][4];  // [slot-in-half][i][k]
#pragma unroll
                for (int k = 0; k < 4; k++) {
                    ulonglong2 U =
                        *(const ulonglong2*)&su[bf][jj + k][bg * 8 + h * 4];
                    ulonglong2 V =
                        *(const ulonglong2*)&sv[bf][jj + k][bg * 8 + h * 4];
                    d[0][0][k] = fma2(U.x, P[k][0], fma2(V.x, Q[k][0], C22));
                    d[0][1][k] = fma2(U.x, P[k][1], fma2(V.x, Q[k][1], C22));
                    d[1][0][k] = fma2(U.y, P[k][0], fma2(V.y, Q[k][0], C22));
                    d[1][1][k] = fma2(U.y, P[k][1], fma2(V.y, Q[k][1], C22));
                }
#pragma unroll
                for (int si = 0; si < 2; si++)
#pragma unroll
                    for (int i = 0; i < 2; i++)
                        QCOMB(acc[h * 2 + si][i], d[si][i][0], d[si][i][1],
                              d[si][i][2], d[si][i][3]);
            }
        }

        if (c + 1 < NCH) __syncthreads();
    }

    // Flush: slot s -> rows b0 + bg*8 + 2s + {0,1} (lanes lo/hi);
    // cols i0 + ig*2 + {0,1}; partial sums via red.v2 along i.
#pragma unroll
    for (int s = 0; s < 4; s++) {
        float l0, h0, l1, h1;
        unpack2(acc[s][0], l0, h0);
        unpack2(acc[s][1], l1, h1);
        int row = b0 + bg * 8 + 2 * s;
        float* op = out + (size_t)row * ODIM + i0 + ig * 2;
        redadd2(op, D * l0, D * l1);
        redadd2(op + ODIM, D * h0, D * h1);
    }
}

extern "C" void kernel_launch(void* const* d_in, const int* in_sizes, int n_in,
                              void* d_out, int out_size) {
    const float* x   = (const float*)d_in[0];  // input_matrix [2048, 256]
    const float* off = (const float*)d_in[1];  // phase_offset [256, 256]
    float* out = (float*)d_out;                // [2048, 256]

    const double PI = 3.14159265358979323846;
    const double RADIUS = 5e-6, KAPPA = 0.1, N_EFF = 3.48, LAMBDA = 1.55e-6,
                 LOSS_A = 0.99;
    double t = sqrt(1.0 - KAPPA);
    double at = LOSS_A * t;
    float K  = (float)(2.0 * at);
    float C2 = (float)(1.0 + at * at);
    float D  = (float)(-(1.0 - t * t) * (1.0 - LOSS_A * LOSS_A));
    float phi0 = (float)fmod(2.0 * PI * N_EFF * (2.0 * PI * RADIUS) / LAMBDA,
                             2.0 * PI);

    prep_all<<<1088, 256>>>(x, off, out, K, phi0);
    photonic_main<<<2048, 128>>>(out, C2, D);
}

// round 17
// speedup vs baseline: 1.3187x; 1.3187x over previous
#include <cuda_runtime.h>
#include <math.h>

#define BDIM 2048
#define ODIM 256
#define IDIM 256

typedef unsigned long long u64;
typedef unsigned int u32;

// Scratch. g_u[j][b] = -K*cos(phi0+x[b,j]); g_v[j][b] = K*sin(phi0+x[b,j])
// g_pd[j][2i..2i+1] = dup cos(off[i,j]); g_qd = dup sin(off[i,j])
__device__ float g_u[IDIM * BDIM];
__device__ float g_v[IDIM * BDIM];
__device__ float g_pd[IDIM * 2 * ODIM];
__device__ float g_qd[IDIM * 2 * ODIM];

// ---------- packed f32x2 helpers ----------
__device__ __forceinline__ u64 fma2(u64 a, u64 b, u64 c) {
    u64 d;
    asm("fma.rn.f32x2 %0, %1, %2, %3;" : "=l"(d) : "l"(a), "l"(b), "l"(c));
    return d;
}
__device__ __forceinline__ u64 add2(u64 a, u64 b) {
    u64 d;
    asm("add.rn.f32x2 %0, %1, %2;" : "=l"(d) : "l"(a), "l"(b));
    return d;
}
__device__ __forceinline__ u64 mul2(u64 a, u64 b) {
    u64 d;
    asm("mul.rn.f32x2 %0, %1, %2;" : "=l"(d) : "l"(a), "l"(b));
    return d;
}
__device__ __forceinline__ float frcp(float x) {
    float r;
    asm("rcp.approx.ftz.f32 %0, %1;" : "=f"(r) : "f"(x));
    return r;
}
__device__ __forceinline__ u64 rcp2(u64 x) {
    float lo, hi;
    asm("mov.b64 {%0, %1}, %2;" : "=f"(lo), "=f"(hi) : "l"(x));
    lo = frcp(lo);
    hi = frcp(hi);
    u64 r;
    asm("mov.b64 %0, {%1, %2};" : "=l"(r) : "f"(lo), "f"(hi));
    return r;
}
__device__ __forceinline__ u64 pack2(float lo, float hi) {
    u64 r;
    asm("mov.b64 %0, {%1, %2};" : "=l"(r) : "f"(lo), "f"(hi));
    return r;
}
__device__ __forceinline__ void unpack2(u64 v, float& lo, float& hi) {
    asm("mov.b64 {%0, %1}, %2;" : "=f"(lo), "=f"(hi) : "l"(v));
}

// fire-and-forget vector reduction (REDG.64), sm_90+
__device__ __forceinline__ void redadd2(float* p, float a, float b) {
    asm volatile("red.global.add.v2.f32 [%0], {%1, %2};" ::"l"(p), "f"(a),
                 "f"(b)
                 : "memory");
}

// ---------- cp.async (LDGSTS) ----------
__device__ __forceinline__ void cpasync16(u32 saddr, const void* gptr) {
    asm volatile("cp.async.cg.shared.global [%0], [%1], 16;" ::"r"(saddr),
                 "l"(gptr));
}
#define CP_COMMIT() asm volatile("cp.async.commit_group;" ::: "memory")
#define CP_WAIT(N) asm volatile("cp.async.wait_group %0;" ::"n"(N) : "memory")

// ---------- fused prep: uv transpose (512) + pq dup transpose (64) + init (512)
__global__ void prep_all(const float* __restrict__ x,
                         const float* __restrict__ off,
                         float* __restrict__ out, float K, float phi0) {
    const int bx = blockIdx.x;
    if (bx < 512) {
        __shared__ float tc[32][33];
        __shared__ float ts[32][33];
        const int b0 = (bx >> 3) * 32;
        const int j0 = (bx & 7) * 32;
#pragma unroll
        for (int k = 0; k < 4; k++) {
            int lin = threadIdx.x + k * 256;
            int bl = lin >> 5, jl = lin & 31;
            float s, c;
            __sincosf(phi0 + x[(b0 + bl) * IDIM + j0 + jl], &s, &c);
            tc[jl][bl] = c;
            ts[jl][bl] = s;
        }
        __syncthreads();
#pragma unroll
        for (int k = 0; k < 4; k++) {
            int lin = threadIdx.x + k * 256;
            int jl = lin >> 5, bl = lin & 31;
            g_u[(j0 + jl) * BDIM + b0 + bl] = -K * tc[jl][bl];
            g_v[(j0 + jl) * BDIM + b0 + bl] = K * ts[jl][bl];
        }
    } else if (bx < 576) {
        __shared__ float tc[32][33];
        __shared__ float ts[32][33];
        const int r = bx - 512;
        const int i0 = (r >> 3) * 32;
        const int j0 = (r & 7) * 32;
#pragma unroll
        for (int k = 0; k < 4; k++) {
            int lin = threadIdx.x + k * 256;
            int il = lin >> 5, jl = lin & 31;
            float s, c;
            __sincosf(off[(i0 + il) * IDIM + j0 + jl], &s, &c);
            tc[jl][il] = c;
            ts[jl][il] = s;
        }
        __syncthreads();
#pragma unroll
        for (int k = 0; k < 4; k++) {
            int lin = threadIdx.x + k * 256;
            int jl = lin >> 5, il = lin & 31;
            float c = tc[jl][il], s = ts[jl][il];
            float2 cc = {c, c}, ss = {s, s};
            *(float2*)&g_pd[(j0 + jl) * (2 * ODIM) + 2 * (i0 + il)] = cc;
            *(float2*)&g_qd[(j0 + jl) * (2 * ODIM) + 2 * (i0 + il)] = ss;
        }
    } else {
        // init out = IDIM (base of T-sum); 512 blocks x 256 thr x float4
        int idx = (bx - 576) * 256 + threadIdx.x;
        float4 v = {(float)IDIM, (float)IDIM, (float)IDIM, (float)IDIM};
        ((float4*)out)[idx] = v;
    }
}

// triple combine: 1/d0+1/d1+1/d2 = (m01 + d2*s01) / (m01*d2)
#define QCOMB3(ACC, D0, D1, D2)                                         \
    do {                                                                \
        u64 s01 = add2(D0, D1), m01 = mul2(D0, D1);                     \
        u64 num = fma2(D2, s01, m01);                                   \
        u64 den = mul2(m01, D2);                                        \
        ACC = fma2(num, rcp2(den), ACC);                                \
    } while (0)

// quad combine: acc += (s01*m23 + s23*m01) * rcp(m01*m23)
#define QCOMB4(ACC, D0, D1, D2, D3)                                     \
    do {                                                                \
        u64 s01 = add2(D0, D1), m01 = mul2(D0, D1);                     \
        u64 s23 = add2(D2, D3), m23 = mul2(D2, D3);                     \
        u64 num = fma2(s23, m01, mul2(s01, m23));                       \
        u64 den = mul2(m01, m23);                                       \
        ACC = fma2(num, rcp2(den), ACC);                                \
    } while (0)

// load U/V slot-pairs and dup P/Q pairs for one j, compute 4 packed d's
#define DGEN(JROW)                                                      \
    {                                                                   \
        ulonglong2 Ut = *(const ulonglong2*)&su[bf][JROW][bg * 4];      \
        ulonglong2 Vt = *(const ulonglong2*)&sv[bf][JROW][bg * 4];      \
        ulonglong2 Pt = *(const ulonglong2*)&spd[bf][JROW][ig * 8 + t2 * 4]; \
        ulonglong2 Qt = *(const ulonglong2*)&sqd[bf][JROW][ig * 8 + t2 * 4]; \
        dxl[kk] = fma2(Ut.x, Pt.x, fma2(Vt.x, Qt.x, C22));              \
        dxh[kk] = fma2(Ut.x, Pt.y, fma2(Vt.x, Qt.y, C22));              \
        dyl[kk] = fma2(Ut.y, Pt.x, fma2(Vt.y, Qt.x, C22));              \
        dyh[kk] = fma2(Ut.y, Pt.y, fma2(Vt.y, Qt.y, C22));              \
    }

// ---------- main: BM=32 x BN=64 x 32j work units, 128 threads --------------
// grid = 2048: bits[0:2] = k-part (32 j), bits[3..] = spatial (4 i x 64 b).
// Per thread: 4 b (2 packed slots) x 4 i -> 8 packed accumulators.
// Inner: chunk of 16 j = 4 triples + 1 quad (rational j-combining).
__global__ __launch_bounds__(128, 4) void photonic_main(float* __restrict__ out,
                                                        float C2, float D) {
    __shared__ float su[2][16][32];
    __shared__ float sv[2][16][32];
    __shared__ float spd[2][16][128];
    __shared__ float sqd[2][16][128];

    const int tid = threadIdx.x;
    const int bg = tid & 7;    // 8 b-groups x 4 b
    const int ig = tid >> 3;   // 16 i-groups x 4 i
    const int kpart = blockIdx.x & 7;
    const int spat = blockIdx.x >> 3;  // 0..255
    const int i0 = (spat & 3) * 64;
    const int b0 = (spat >> 2) * 32;
    const int jbase = kpart * 32;

    const u64 C22 = pack2(C2, C2);
    u64 acc[2][4];  // [b-slot][i]
#pragma unroll
    for (int s = 0; s < 2; s++)
#pragma unroll
        for (int i = 0; i < 4; i++) acc[s][i] = 0ull;

    auto cp_chunk = [&](int kc, int bf) {
        const int j0 = jbase + kc * 16;
        // su/sv: 512 floats each -> 1 x 16B per thread
        {
            int r = tid >> 3, c = (tid & 7) * 4;
            cpasync16((u32)__cvta_generic_to_shared(&su[bf][r][c]),
                      g_u + (size_t)(j0 + r) * BDIM + b0 + c);
            cpasync16((u32)__cvta_generic_to_shared(&sv[bf][r][c]),
                      g_v + (size_t)(j0 + r) * BDIM + b0 + c);
        }
        // spd/sqd: 2048 floats each -> 4 x 16B per thread
#pragma unroll
        for (int k = 0; k < 4; k++) {
            int idx = tid + 128 * k;
            int r = idx >> 5, c = (idx & 31) * 4;
            cpasync16((u32)__cvta_generic_to_shared(&spd[bf][r][c]),
                      g_pd + (size_t)(j0 + r) * (2 * ODIM) + 2 * i0 + c);
            cpasync16((u32)__cvta_generic_to_shared(&sqd[bf][r][c]),
                      g_qd + (size_t)(j0 + r) * (2 * ODIM) + 2 * i0 + c);
        }
        CP_COMMIT();
    };

    cp_chunk(0, 0);

    const int NCH = 2;  // 32 j / 16
    for (int c = 0; c < NCH; c++) {
        const int bf = c & 1;
        if (c + 1 < NCH) {
            cp_chunk(c + 1, bf ^ 1);
            CP_WAIT(1);
        } else {
            CP_WAIT(0);
        }
        __syncthreads();

        // 4 triples: j = 0..11
#pragma unroll
        for (int g = 0; g < 4; g++) {
            const int jj = g * 3;
#pragma unroll
            for (int t2 = 0; t2 < 2; t2++) {
                u64 dxl[3], dxh[3], dyl[3], dyh[3];
#pragma unroll
                for (int kk = 0; kk < 3; kk++) DGEN(jj + kk);
                QCOMB3(acc[0][2 * t2], dxl[0], dxl[1], dxl[2]);
                QCOMB3(acc[0][2 * t2 + 1], dxh[0], dxh[1], dxh[2]);
                QCOMB3(acc[1][2 * t2], dyl[0], dyl[1], dyl[2]);
                QCOMB3(acc[1][2 * t2 + 1], dyh[0], dyh[1], dyh[2]);
            }
        }
        // quad tail: j = 12..15
        {
            const int jj = 12;
#pragma unroll
            for (int t2 = 0; t2 < 2; t2++) {
                u64 dxl[4], dxh[4], dyl[4], dyh[4];
#pragma unroll
                for (int kk = 0; kk < 4; kk++) DGEN(jj + kk);
                QCOMB4(acc[0][2 * t2], dxl[0], dxl[1], dxl[2], dxl[3]);
                QCOMB4(acc[0][2 * t2 + 1], dxh[0], dxh[1], dxh[2], dxh[3]);
                QCOMB4(acc[1][2 * t2], dyl[0], dyl[1], dyl[2], dyl[3]);
                QCOMB4(acc[1][2 * t2 + 1], dyh[0], dyh[1], dyh[2], dyh[3]);
            }
        }

        if (c + 1 < NCH) __syncthreads();
    }

    // Flush: slot s -> rows b0 + bg*4 + 2s + {0,1} (lanes lo/hi);
    // cols i0 + ig*4 + {0..3}; partial sums via red.v2 along i.
#pragma unroll
    for (int s = 0; s < 2; s++) {
        float l[4], h[4];
#pragma unroll
        for (int i = 0; i < 4; i++) unpack2(acc[s][i], l[i], h[i]);
        int row = b0 + bg * 4 + 2 * s;
        float* op = out + (size_t)row * ODIM + i0 + ig * 4;
        redadd2(op, D * l[0], D * l[1]);
        redadd2(op + 2, D * l[2], D * l[3]);
        redadd2(op + ODIM, D * h[0], D * h[1]);
        redadd2(op + ODIM + 2, D * h[2], D * h[3]);
    }
}

extern "C" void kernel_launch(void* const* d_in, const int* in_sizes, int n_in,
                              void* d_out, int out_size) {
    const float* x   = (const float*)d_in[0];  // input_matrix [2048, 256]
    const float* off = (const float*)d_in[1];  // phase_offset [256, 256]
    float* out = (float*)d_out;                // [2048, 256]

    const double PI = 3.14159265358979323846;
    const double RADIUS = 5e-6, KAPPA = 0.1, N_EFF = 3.48, LAMBDA = 1.55e-6,
                 LOSS_A = 0.99;
    double t = sqrt(1.0 - KAPPA);
    double at = LOSS_A * t;
    float K  = (float)(2.0 * at);
    float C2 = (float)(1.0 + at * at);
    float D  = (float)(-(1.0 - t * t) * (1.0 - LOSS_A * LOSS_A));
    float phi0 = (float)fmod(2.0 * PI * N_EFF * (2.0 * PI * RADIUS) / LAMBDA,
                             2.0 * PI);

    prep_all<<<1088, 256>>>(x, off, out, K, phi0);
    photonic_main<<<2048, 128>>>(out, C2, D);
}